// round 17
// baseline (speedup 1.0000x reference)
#include <cuda_runtime.h>

#define NB   64
#define SEQ  512
#define DIM  64
#define BIGF 1e30f
#define LOG2E 1.44269504088896340736f
#define LN2   0.69314718055994530942f

#define LEAD   24         // cp.async pipeline depth in beats
#define LEADM2 22         // wait_group bound: completed >= idx+3 columns
#define RSLOT  64         // ring slots (power of 2)
#define CBYTES 2064       // bytes per ring column (516 words: 4-way LDS conflicts max)
#define RING_BYTES (RSLOT * CBYTES)   // 132096

typedef unsigned long long u64;

// Scratch (static device globals — allocation-free per harness rules)
// TRANSPOSED layout: g_D[b][j][i]  (column j contiguous in i)
__device__ float g_D[(size_t)NB * SEQ * SEQ];
__device__ float g_x2[NB * SEQ];
__device__ float g_y2[NB * SEQ];

// ---------------------------------------------------------------------------
// helpers
// ---------------------------------------------------------------------------
__device__ __forceinline__ u64 ffma2(u64 a, u64 b, u64 c) {
    u64 d;
    asm("fma.rn.f32x2 %0, %1, %2, %3;" : "=l"(d) : "l"(a), "l"(b), "l"(c));
    return d;
}
__device__ __forceinline__ u64 pack2(float lo, float hi) {
    u64 d;
    asm("mov.b64 %0, {%1, %2};" : "=l"(d) : "f"(lo), "f"(hi));
    return d;
}
__device__ __forceinline__ float2 unpack2(u64 v) {
    float2 r;
    asm("mov.b64 {%0, %1}, %2;" : "=f"(r.x), "=f"(r.y) : "l"(v));
    return r;
}
__device__ __forceinline__ float ex2(float x) {
    float r; asm("ex2.approx.ftz.f32 %0, %1;" : "=f"(r) : "f"(x)); return r;
}
__device__ __forceinline__ float lg2(float x) {
    float r; asm("lg2.approx.ftz.f32 %0, %1;" : "=f"(r) : "f"(x)); return r;
}
__device__ __forceinline__ void cpasync16(unsigned int dst, const void* src) {
    asm volatile("cp.async.cg.shared.global [%0], [%1], 16;" :: "r"(dst), "l"(src));
}
#define CP_COMMIT() asm volatile("cp.async.commit_group;" ::: "memory")
#define CP_WAIT(N)  asm volatile("cp.async.wait_group %0;" :: "n"(N) : "memory")

// ---------------------------------------------------------------------------
// Kernel 0: row norms. 8 threads per row, 32 rows per 256-thread block.
// ---------------------------------------------------------------------------
__global__ __launch_bounds__(256) void rownorm_kernel(const float* __restrict__ A, int which) {
    int row = blockIdx.x * 32 + (threadIdx.x >> 3);
    int l = threadIdx.x & 7;
    const float4* a = (const float4*)(A + (size_t)row * DIM);
    float4 v1 = __ldg(&a[l * 2]);
    float4 v2 = __ldg(&a[l * 2 + 1]);
    float s = v1.x*v1.x + v1.y*v1.y + v1.z*v1.z + v1.w*v1.w
            + v2.x*v2.x + v2.y*v2.y + v2.z*v2.z + v2.w*v2.w;
    s += __shfl_down_sync(0xffffffffu, s, 4);
    s += __shfl_down_sync(0xffffffffu, s, 2);
    s += __shfl_down_sync(0xffffffffu, s, 1);
    if (l == 0) {
        float* out = which ? g_y2 : g_x2;
        out[row] = s;
    }
}

// ---------------------------------------------------------------------------
// Kernel 1: pairwise squared distances with packed f32x2 FFMA2.
// Writes TRANSPOSED + log2e-scaled: D_t[b][j][i] = log2e*(x2[i]+y2[j]-2*dot).
// ---------------------------------------------------------------------------
#define BM 128
#define BN 128
#define BK 16
#define STRX 34
#define STRY 34
#define TPAD 132

__global__ __launch_bounds__(256, 2) void pairdist_kernel(const float* __restrict__ X,
                                                          const float* __restrict__ Y) {
    __shared__ __align__(16) float Xs2[BM * STRX];
    __shared__ float Ys2[64 * STRY];

    int b  = blockIdx.z;
    int i0 = blockIdx.y * BM;
    int j0 = blockIdx.x * BN;
    const float* Xb = X + (size_t)b * SEQ * DIM + (size_t)i0 * DIM;
    const float* Yb = Y + (size_t)b * SEQ * DIM + (size_t)j0 * DIM;

    int tid = threadIdx.x;
    int tx = tid & 15;
    int ty = tid >> 4;

    u64 acc2[8][4];
#pragma unroll
    for (int r = 0; r < 8; r++)
#pragma unroll
        for (int c2 = 0; c2 < 4; c2++) acc2[r][c2] = 0ull;

    for (int k0 = 0; k0 < DIM; k0 += BK) {
        __syncthreads();
#pragma unroll
        for (int q = 0; q < 2; q++) {
            int idx = tid + q * 256;
            int r  = idx >> 2;
            int c4 = idx & 3;
            float4 xv = __ldg((const float4*)(Xb + (size_t)r * DIM + k0 + c4 * 4));
            float4 yv = __ldg((const float4*)(Yb + (size_t)r * DIM + k0 + c4 * 4));
            u64* xs = (u64*)&Xs2[r * STRX + c4 * 8];
            xs[0] = pack2(xv.x, xv.x);
            xs[1] = pack2(xv.y, xv.y);
            xs[2] = pack2(xv.z, xv.z);
            xs[3] = pack2(xv.w, xv.w);
            int pr   = (r & 15) + 16 * (r >> 5);
            int slot = (r >> 4) & 1;
            float* ys = &Ys2[pr * STRY + c4 * 8 + slot];
            ys[0] = yv.x; ys[2] = yv.y; ys[4] = yv.z; ys[6] = yv.w;
        }
        __syncthreads();

#pragma unroll
        for (int k = 0; k < BK; k++) {
            u64 bb[4];
#pragma unroll
            for (int c2 = 0; c2 < 4; c2++)
                bb[c2] = *(const u64*)&Ys2[(tx + 16 * c2) * STRY + k * 2];
#pragma unroll
            for (int r = 0; r < 8; r++) {
                u64 aa = *(const u64*)&Xs2[(ty + 16 * r) * STRX + k * 2];
#pragma unroll
                for (int c2 = 0; c2 < 4; c2++)
                    acc2[r][c2] = ffma2(aa, bb[c2], acc2[r][c2]);
            }
        }
    }

    float yn[8];
#pragma unroll
    for (int c = 0; c < 8; c++) yn[c] = g_y2[b * SEQ + j0 + tx + 16 * c];
    float xnr[8];
#pragma unroll
    for (int r = 0; r < 8; r++) xnr[r] = g_x2[b * SEQ + i0 + ty + 16 * r];

    float* Dt = g_D + (size_t)b * SEQ * SEQ;
    float* T  = Xs2;

    __syncthreads();
#pragma unroll
    for (int q = 0; q < 4; q++) {
#pragma unroll
        for (int r = 0; r < 8; r++) {
            int ii = ty + 16 * r;
            float2 d2 = unpack2(acc2[r][q]);
            T[tx * TPAD + ii]        = LOG2E * (xnr[r] + yn[2 * q]     - 2.0f * d2.x);
            T[(tx + 16) * TPAD + ii] = LOG2E * (xnr[r] + yn[2 * q + 1] - 2.0f * d2.y);
        }
        __syncthreads();
#pragma unroll
        for (int v = 0; v < 4; v++) {
            int jj2 = tid >> 3;
            int ii2 = (tid & 7) * 16 + v * 4;
            float4 t = *(float4*)&T[jj2 * TPAD + ii2];
            *(float4*)&Dt[(size_t)(j0 + 32 * q + jj2) * SEQ + i0 + ii2] = t;
        }
        __syncthreads();
    }
}

// ---------------------------------------------------------------------------
// Kernel 2: soft-DTW, sync-free, one warp/batch, 16 rows/lane — R16 compute
// path, with the memory system replaced by a cp.async smem ring:
//   * each beat the warp issues 4 COALESCED cp.async (16 B/lane) fetching the
//     full column idx+LEAD into ring slot (idx+LEAD)&63 (16 lines vs 128
//     scattered before; 100% byte utilization; ~LEAD-beat latency budget)
//   * cp.async.wait_group(LEADM2) each beat proves columns <= idx+2 resident
//   * next beat's 16 d-values per lane come from 4 LDS.128 (4-way conflicts)
// Ring slot reuse distance = 64-LEAD = 40 > 32 (max lane lag) — safe.
// ---------------------------------------------------------------------------
#define FCELL(NV, VOLD, DV) {                                        \
    float l_ = (VOLD); float lo_ = fminf(u, l_), hi_ = fmaxf(u, l_); \
    float mn_ = fminf(a, lo_), m1_ = fmaxf(a, lo_);                  \
    gmin = fminf(gmin, fminf(m1_, hi_) - mn_);                       \
    NV = (DV) + mn_; a = l_; u = NV; }

#define XCELL(NV, VOLD, DV) {                                        \
    float l_ = (VOLD); float lo_ = fminf(u, l_), hi_ = fmaxf(u, l_); \
    float mn_ = fminf(a, lo_), m1_ = fmaxf(a, lo_);                  \
    float s_ = 1.0f + ex2(mn_ - m1_) + ex2(mn_ - hi_);               \
    NV = (DV) + mn_ - lg2(s_); a = l_; u = NV; }

#define ALL16(M)                                                     \
    M(nv0,  v0,  Ca.x) M(nv1,  v1,  Ca.y) M(nv2,  v2,  Ca.z) M(nv3,  v3,  Ca.w) \
    M(nv4,  v4,  Cb.x) M(nv5,  v5,  Cb.y) M(nv6,  v6,  Cb.z) M(nv7,  v7,  Cb.w) \
    M(nv8,  v8,  Cc.x) M(nv9,  v9,  Cc.y) M(nv10, v10, Cc.z) M(nv11, v11, Cc.w) \
    M(nv12, v12, Cd.x) M(nv13, v13, Cd.y) M(nv14, v14, Cd.z) M(nv15, v15, Cd.w)

#define COMMIT16() { v0=nv0; v1=nv1; v2=nv2; v3=nv3; v4=nv4; v5=nv5; v6=nv6;   \
    v7=nv7; v8=nv8; v9=nv9; v10=nv10; v11=nv11; v12=nv12; v13=nv13; v14=nv14;  \
    v15=nv15; }

#define BEAT(IDX, GUARDED) {                                                   \
    float sh = __shfl_up_sync(0xffffffffu, v15, 1);                            \
    if (lane == 0) sh = BIGF;                                                  \
    int j_ = (IDX) - lane;                                                     \
    if (!(GUARDED) || (j_ >= 0 && j_ < SEQ)) {                                 \
        float a = shp, u = sh, gmin = BIGF;                                    \
        ALL16(FCELL)                                                           \
        if (gmin < 8.0f) { a = shp; u = sh; ALL16(XCELL) }                     \
        COMMIT16()                                                             \
        if ((GUARDED) && lane == 31 && j_ == SEQ - 1) out[b] = v15 * LN2;      \
    }                                                                          \
    shp = sh;                                                                  \
    { int cf_ = (IDX) + LEAD;                                                  \
      if (cf_ < SEQ) {                                                         \
        unsigned int d_ = rbase + (unsigned int)((cf_ & (RSLOT-1)) * CBYTES + lane * 16); \
        const float* s_ = Dt + (size_t)cf_ * SEQ + lane * 4;                   \
        cpasync16(d_,        s_);                                              \
        cpasync16(d_ + 512,  s_ + 128);                                        \
        cpasync16(d_ + 1024, s_ + 256);                                        \
        cpasync16(d_ + 1536, s_ + 384);                                        \
      }                                                                        \
      CP_COMMIT();                                                             \
      CP_WAIT(LEADM2);                                                         \
      int cn_ = ((IDX) + 1 - lane + RSLOT) & (RSLOT - 1);                      \
      const float4* p_ = (const float4*)((const char*)ring + cn_ * CBYTES + lane * 64); \
      Ca = p_[0]; Cb = p_[1]; Cc = p_[2]; Cd = p_[3]; } }

extern __shared__ float ring[];

__global__ __launch_bounds__(32, 1) void softdtw_kernel(float* __restrict__ out) {
    int b    = blockIdx.x;
    int lane = threadIdx.x;

    unsigned int rbase;
    asm("{ .reg .u64 t; cvta.to.shared.u64 t, %1; cvt.u32.u64 %0, t; }"
        : "=r"(rbase) : "l"(ring));

    const float* Dt = g_D + (size_t)b * SEQ * SEQ;

    float v0=BIGF,v1=BIGF,v2=BIGF,v3=BIGF,v4=BIGF,v5=BIGF,v6=BIGF,v7=BIGF,
          v8=BIGF,v9=BIGF,v10=BIGF,v11=BIGF,v12=BIGF,v13=BIGF,v14=BIGF,v15=BIGF;
    float nv0,nv1,nv2,nv3,nv4,nv5,nv6,nv7,nv8,nv9,nv10,nv11,nv12,nv13,nv14,nv15;
    float shp = (lane == 0) ? 0.0f : BIGF;   // R(16*lane-1, j-1); (0,0) diag = 0

    // ---- warm-up: prefetch columns 0..LEAD-1 (one commit group each) ----
    for (int c = 0; c < LEAD; c++) {
        unsigned int d_ = rbase + (unsigned int)(c * CBYTES + lane * 16);
        const float* s_ = Dt + (size_t)c * SEQ + lane * 4;
        cpasync16(d_,        s_);
        cpasync16(d_ + 512,  s_ + 128);
        cpasync16(d_ + 1024, s_ + 256);
        cpasync16(d_ + 1536, s_ + 384);
        CP_COMMIT();
    }
    CP_WAIT(LEADM2);   // columns 0 and 1 resident

    // preload beat-0 d (lane l: column -l, wrapped; garbage for l>0, unused)
    float4 Ca, Cb, Cc, Cd;
    {
        int cn_ = ((0 - lane) + RSLOT) & (RSLOT - 1);
        const float4* p_ = (const float4*)((const char*)ring + cn_ * CBYTES + lane * 64);
        Ca = p_[0]; Cb = p_[1]; Cc = p_[2]; Cd = p_[3];
    }

    int idx = 0;
    // warm-up beats 0..32 (guarded)
#pragma unroll 1
    for (int t = 0; t < 33; t++) { BEAT(idx, 1) idx++; }
    // steady beats 33..509 (all lanes active, no guard)
#pragma unroll 1
    for (int t = 0; t < 477; t++) { BEAT(idx, 0) idx++; }
    // tail beats 510..542 (guarded; final output at idx=542, lane 31)
#pragma unroll 1
    for (int t = 0; t < 33; t++) { BEAT(idx, 1) idx++; }
}

// ---------------------------------------------------------------------------
extern "C" void kernel_launch(void* const* d_in, const int* in_sizes, int n_in,
                              void* d_out, int out_size) {
    const float* x = (const float*)d_in[0];
    const float* y = (const float*)d_in[1];
    float* out = (float*)d_out;

    static int smem_set = 0;
    if (!smem_set) {
        cudaFuncSetAttribute(softdtw_kernel,
                             cudaFuncAttributeMaxDynamicSharedMemorySize, RING_BYTES);
        smem_set = 1;
    }

    rownorm_kernel<<<NB * SEQ / 32, 256>>>(x, 0);
    rownorm_kernel<<<NB * SEQ / 32, 256>>>(y, 1);

    dim3 g(SEQ / BN, SEQ / BM, NB);
    pairdist_kernel<<<g, 256>>>(x, y);

    softdtw_kernel<<<NB, 32, RING_BYTES>>>(out);
}